// round 1
// baseline (speedup 1.0000x reference)
#include <cuda_runtime.h>
#include <cstdint>

// Problem dims
#define B_BATCH   128
#define T_STEPS   500
#define K_DIM     700      // in_features
#define N_DIM     1024     // out_features (hidden)
#define M_DIM     (B_BATCH * T_STEPS)   // 64000

// LIF constants (fp32 rounding of float(np.exp(-dt/tau)))
#define PHI_C    0.36787944117144233f   // exp(-1)
#define GAMMA_C  0.8187307530779818f    // exp(-0.2)
#define BETA_C   0.9048374180359595f    // exp(-0.1)
#define U_TH_C   1.0f

// Scratch: inputs[b,t,h] = X @ W^T   (64000 x 1024 fp32 = 262 MB)
__device__ float g_inputs[(size_t)M_DIM * N_DIM];

// ---------------------------------------------------------------------------
// GEMM:  C[m,n] = sum_k A[m,k] * B[n,k]    (NT, fp32, exact FMA)
// Tiles: BM=128, BN=128, BK=16, 256 threads, 8x8 micro-tile per thread.
// Inner product uses packed fma.rn.f32x2 (2 FMA lanes per instruction).
// ---------------------------------------------------------------------------
#define BM 128
#define BN 128
#define BK 16
#define SPAD 4   // smem row padding to avoid 4-way bank conflict on transposed store

__global__ __launch_bounds__(256) void gemm_nt_kernel(
    const float* __restrict__ A,   // [M_DIM, K_DIM]
    const float* __restrict__ Bw,  // [N_DIM, K_DIM]
    float* __restrict__ C)         // [M_DIM, N_DIM]
{
    __shared__ float As[BK][BM + SPAD];
    __shared__ float Bs[BK][BN + SPAD];

    const int tid = threadIdx.x;
    const int tx  = tid & 15;        // 0..15 -> n micro-tile
    const int ty  = tid >> 4;        // 0..15 -> m micro-tile
    const int m0  = blockIdx.y * BM; // M_DIM % BM == 0
    const int n0  = blockIdx.x * BN; // N_DIM % BN == 0

    // 8 rows x 4 packed col-pairs of f32x2 accumulators
    unsigned long long acc[8][4];
#pragma unroll
    for (int i = 0; i < 8; i++)
#pragma unroll
        for (int j = 0; j < 4; j++) acc[i][j] = 0ULL;

    for (int kk = 0; kk < K_DIM; kk += BK) {
        // ---- load A tile: 128 rows x 16 k  (512 float4, 2 per thread) ----
#pragma unroll
        for (int l = 0; l < 2; l++) {
            int f   = tid + l * 256;
            int row = f >> 2;
            int kq  = f & 3;
            int kg  = kk + kq * 4;
            float4 v = make_float4(0.f, 0.f, 0.f, 0.f);
            if (kg < K_DIM)   // K_DIM % 4 == 0, so whole float4 in-bounds
                v = *(const float4*)(A + (size_t)(m0 + row) * K_DIM + kg);
            As[kq * 4 + 0][row] = v.x;
            As[kq * 4 + 1][row] = v.y;
            As[kq * 4 + 2][row] = v.z;
            As[kq * 4 + 3][row] = v.w;
        }
        // ---- load B tile ----
#pragma unroll
        for (int l = 0; l < 2; l++) {
            int f   = tid + l * 256;
            int row = f >> 2;
            int kq  = f & 3;
            int kg  = kk + kq * 4;
            float4 v = make_float4(0.f, 0.f, 0.f, 0.f);
            if (kg < K_DIM)
                v = *(const float4*)(Bw + (size_t)(n0 + row) * K_DIM + kg);
            Bs[kq * 4 + 0][row] = v.x;
            Bs[kq * 4 + 1][row] = v.y;
            Bs[kq * 4 + 2][row] = v.z;
            Bs[kq * 4 + 3][row] = v.w;
        }
        __syncthreads();

#pragma unroll
        for (int k = 0; k < BK; k++) {
            // a: 8 floats (2x LDS.128)
            float4 av0 = *(const float4*)&As[k][ty * 8 + 0];
            float4 av1 = *(const float4*)&As[k][ty * 8 + 4];
            float a[8] = {av0.x, av0.y, av0.z, av0.w, av1.x, av1.y, av1.z, av1.w};
            // b: 4 packed pairs (2x LDS.128); (BN+SPAD)=132 -> row base always 8B aligned
            unsigned long long b2[4];
            const unsigned long long* bp =
                (const unsigned long long*)&Bs[k][tx * 8];
            b2[0] = bp[0]; b2[1] = bp[1]; b2[2] = bp[2]; b2[3] = bp[3];
#pragma unroll
            for (int i = 0; i < 8; i++) {
                unsigned long long a2;
                asm("mov.b64 %0, {%1, %1};" : "=l"(a2) : "f"(a[i]));
#pragma unroll
                for (int j = 0; j < 4; j++)
                    asm("fma.rn.f32x2 %0, %1, %2, %0;"
                        : "+l"(acc[i][j]) : "l"(a2), "l"(b2[j]));
            }
        }
        __syncthreads();
    }

    // ---- epilogue: 2x STG.128 per row ----
#pragma unroll
    for (int i = 0; i < 8; i++) {
        float* cp = C + (size_t)(m0 + ty * 8 + i) * N_DIM + n0 + tx * 8;
        *(float4*)(cp + 0) = *(float4*)&acc[i][0];
        *(float4*)(cp + 4) = *(float4*)&acc[i][2];
    }
}

// ---------------------------------------------------------------------------
// LIF scan: one thread per (b, h); sequential over t; coalesced in h.
//   H[t] = PHI*H[t-1] + inp[t-1]
//   I[t] = GAMMA*I[t-1] + H[t-1]
//   U[t] = BETA*(U[t-1] - I[t-1]) - S[t-1]
//   S[t] = (U[t] > 1)
//   U[0] = S[0] = 0
// ---------------------------------------------------------------------------
__global__ __launch_bounds__(256) void lif_scan_kernel(
    const float* __restrict__ inp,  // [B*T, N] == [b, t, h]
    float* __restrict__ Uo,         // [B, T, N]
    float* __restrict__ So)         // [B, T, N]
{
    int idx = blockIdx.x * blockDim.x + threadIdx.x;  // 0 .. B*N-1
    int b = idx >> 10;          // / N_DIM
    int h = idx & (N_DIM - 1);
    size_t base = (size_t)b * T_STEPS * N_DIM + h;

    const float* ip = inp + base;
    float* up = Uo + base;
    float* sp = So + base;

    up[0] = 0.0f;
    sp[0] = 0.0f;

    float H = 0.f, I = 0.f, U = 0.f, S = 0.f;
#pragma unroll 4
    for (int t = 1; t < T_STEPS; t++) {
        float x  = ip[(size_t)(t - 1) * N_DIM];
        float Hn = PHI_C * H + x;
        float In = GAMMA_C * I + H;
        float Un = BETA_C * (U - I) - S;
        float Sn = (Un > U_TH_C) ? 1.0f : 0.0f;
        up[(size_t)t * N_DIM] = Un;
        sp[(size_t)t * N_DIM] = Sn;
        H = Hn; I = In; U = Un; S = Sn;
    }
}

// ---------------------------------------------------------------------------
extern "C" void kernel_launch(void* const* d_in, const int* in_sizes, int n_in,
                              void* d_out, int out_size)
{
    const float* X = (const float*)d_in[0];  // [128, 500, 700]
    const float* W = (const float*)d_in[1];  // [1024, 700]
    float* out = (float*)d_out;              // U then S, each [128,500,1024]

    float* inputs;
    cudaGetSymbolAddress((void**)&inputs, g_inputs);

    dim3 ggrid(N_DIM / BN, M_DIM / BM);      // (8, 500)
    gemm_nt_kernel<<<ggrid, 256>>>(X, W, inputs);

    float* Uo = out;
    float* So = out + (size_t)B_BATCH * T_STEPS * N_DIM;
    int nthreads = B_BATCH * N_DIM;          // 131072
    lif_scan_kernel<<<nthreads / 256, 256>>>(inputs, Uo, So);
}